// round 5
// baseline (speedup 1.0000x reference)
#include <cuda_runtime.h>
#include <cuda_bf16.h>

#define N_RAYS 32768
#define M_G    1024
#define M_PAIRS (M_G / 2)          // 512 gaussian pairs
#define TBL_FLOATS (M_PAIRS * 32)  // 16384 floats = 64 KB
#define SPLITS 8
#define SLOTS  32                  // ray-A slots; ray-B = slot+32 -> 64 rays/block
#define RAYS_PER_BLOCK 64
#define ITERS  (M_PAIRS / SPLITS)  // 64 pair-iterations per thread

// Pair-interleaved coefficient table: pair q, coefficient c (0..15), half h:
//   g_coef[q*32 + c*2 + h] = w_c[2q + h]
// c: 0..3 = C00,C11,C22,C33 | 4..9 = 2C01,2C02,2C03,2C12,2C13,2C23
//    10..13 = l0..l3 | 14 = const (mu^T C mu) | 15 = label
__device__ float g_coef[TBL_FLOATS];

typedef unsigned long long ull;

__device__ __forceinline__ ull pack2(float a, float b) {
    ull r; asm("mov.b64 %0, {%1, %2};" : "=l"(r) : "f"(a), "f"(b)); return r;
}
__device__ __forceinline__ void unpack2(ull v, float& a, float& b) {
    asm("mov.b64 {%0, %1}, %2;" : "=f"(a), "=f"(b) : "l"(v));
}
__device__ __forceinline__ ull fma2(ull a, ull b, ull c) {
    ull d; asm("fma.rn.f32x2 %0, %1, %2, %3;" : "=l"(d) : "l"(a), "l"(b), "l"(c)); return d;
}
__device__ __forceinline__ ull mul2(ull a, ull b) {
    ull d; asm("mul.rn.f32x2 %0, %1, %2;" : "=l"(d) : "l"(a), "l"(b)); return d;
}
__device__ __forceinline__ ull add2(ull a, ull b) {
    ull d; asm("add.rn.f32x2 %0, %1, %2;" : "=l"(d) : "l"(a), "l"(b)); return d;
}

// ---------------------------------------------------------------------------
// Prep: fp32 Gauss-Jordan inverse + one Newton refinement. Folds -0.5*log2(e)
// and the mean into 16 coefficients, written pair-interleaved.
// ---------------------------------------------------------------------------
__global__ void prep_kernel(const float* __restrict__ means,
                            const float* __restrict__ covs,
                            const float* __restrict__ labels) {
    int m = blockIdx.x * blockDim.x + threadIdx.x;
    if (m >= M_G) return;

    float S[4][4], a[4][8];
    #pragma unroll
    for (int i = 0; i < 4; i++)
        #pragma unroll
        for (int j = 0; j < 4; j++) {
            S[i][j] = covs[m * 16 + i * 4 + j];
            a[i][j] = S[i][j];
        }
    #pragma unroll
    for (int i = 0; i < 4; i++)
        #pragma unroll
        for (int j = 0; j < 4; j++) a[i][4 + j] = (i == j) ? 1.0f : 0.0f;

    #pragma unroll
    for (int c = 0; c < 4; c++) {
        float inv = __frcp_rn(a[c][c]);
        #pragma unroll
        for (int j = 0; j < 8; j++) a[c][j] *= inv;
        #pragma unroll
        for (int r = 0; r < 4; r++) {
            if (r == c) continue;
            float f = a[r][c];
            #pragma unroll
            for (int j = 0; j < 8; j++) a[r][j] = fmaf(-f, a[c][j], a[r][j]);
        }
    }
    float X[4][4];
    #pragma unroll
    for (int i = 0; i < 4; i++)
        #pragma unroll
        for (int j = 0; j < 4; j++) X[i][j] = a[i][4 + j];

    // Newton: X <- X * (2I - S*X)
    float T[4][4], Xr[4][4];
    #pragma unroll
    for (int i = 0; i < 4; i++)
        #pragma unroll
        for (int j = 0; j < 4; j++) {
            float s = (i == j) ? 2.0f : 0.0f;
            #pragma unroll
            for (int k = 0; k < 4; k++) s = fmaf(-S[i][k], X[k][j], s);
            T[i][j] = s;
        }
    #pragma unroll
    for (int i = 0; i < 4; i++)
        #pragma unroll
        for (int j = 0; j < 4; j++) {
            float s = 0.0f;
            #pragma unroll
            for (int k = 0; k < 4; k++) s = fmaf(X[i][k], T[k][j], s);
            Xr[i][j] = s;
        }

    const float kk = -0.5f * 1.4426950408889634f;  // -0.5*log2(e)
    float C[4][4];
    #pragma unroll
    for (int i = 0; i < 4; i++)
        #pragma unroll
        for (int j = 0; j < 4; j++) C[i][j] = kk * Xr[i][j];

    float mu[4];
    #pragma unroll
    for (int i = 0; i < 4; i++) mu[i] = means[m * 4 + i];

    float w[16];
    w[0] = C[0][0]; w[1] = C[1][1]; w[2] = C[2][2]; w[3] = C[3][3];
    w[4] = 2.0f * C[0][1]; w[5] = 2.0f * C[0][2]; w[6] = 2.0f * C[0][3];
    w[7] = 2.0f * C[1][2]; w[8] = 2.0f * C[1][3]; w[9] = 2.0f * C[2][3];
    #pragma unroll
    for (int i = 0; i < 4; i++) {
        float s = 0.0f;
        #pragma unroll
        for (int j = 0; j < 4; j++) s = fmaf(C[i][j], mu[j], s);
        w[10 + i] = -2.0f * s;
    }
    float q = 0.0f;
    #pragma unroll
    for (int i = 0; i < 4; i++) {
        float s = 0.0f;
        #pragma unroll
        for (int j = 0; j < 4; j++) s = fmaf(C[i][j], mu[j], s);
        q = fmaf(mu[i], s, q);
    }
    w[14] = q;
    w[15] = labels[m];

    int qp = m >> 1, h = m & 1;
    #pragma unroll
    for (int c = 0; c < 16; c++) g_coef[qp * 32 + c * 2 + h] = w[c];
}

// ---------------------------------------------------------------------------
// Decoder: 256 threads = 32 ray-slots x 8 M-splits; 2 rays/thread.
// Block covers 64 rays; grid = 512; 3 CTAs/SM (24 warps) target.
// Coefficient loads staged 2x LDS.128 to hold regs <= 85.
// ---------------------------------------------------------------------------
extern __shared__ float smem_f[];   // [TBL_FLOATS] table + [512] partials

__global__ void __launch_bounds__(256, 3)
decoder_kernel(const float* __restrict__ origins,
               const float* __restrict__ dirs,
               float* __restrict__ out) {
    const int tid  = threadIdx.x;
    const int slot = tid & (SLOTS - 1);   // 0..31
    const int spl  = tid >> 5;            // 0..7

    // cooperative table load (vectorized)
    {
        const float4* g4 = reinterpret_cast<const float4*>(g_coef);
        float4* s4 = reinterpret_cast<float4*>(smem_f);
        #pragma unroll
        for (int i = 0; i < TBL_FLOATS / 4 / 256; i++)
            s4[tid + i * 256] = g4[tid + i * 256];
    }
    float* s_red = smem_f + TBL_FLOATS;   // [SPLITS][64]
    __syncthreads();

    const int base = blockIdx.x * RAYS_PER_BLOCK;
    const int nA = base + slot;
    const int nB = base + slot + SLOTS;

    const float2 oA = reinterpret_cast<const float2*>(origins)[nA];
    const float2 dA = reinterpret_cast<const float2*>(dirs)[nA];
    const float2 oB = reinterpret_cast<const float2*>(origins)[nB];
    const float2 dB = reinterpret_cast<const float2*>(dirs)[nB];

    const float a0p = oA.x, a1p = oA.y, a2p = dA.x, a3p = dA.y;
    const float b0p = oB.x, b1p = oB.y, b2p = dB.x, b3p = dB.y;

    // duplicated packed monomials, ray A
    const ull AF00 = pack2(a0p*a0p, a0p*a0p), AF11 = pack2(a1p*a1p, a1p*a1p);
    const ull AF22 = pack2(a2p*a2p, a2p*a2p), AF33 = pack2(a3p*a3p, a3p*a3p);
    const ull AF01 = pack2(a0p*a1p, a0p*a1p), AF02 = pack2(a0p*a2p, a0p*a2p);
    const ull AF03 = pack2(a0p*a3p, a0p*a3p), AF12 = pack2(a1p*a2p, a1p*a2p);
    const ull AF13 = pack2(a1p*a3p, a1p*a3p), AF23 = pack2(a2p*a3p, a2p*a3p);
    const ull AP0 = pack2(a0p, a0p), AP1 = pack2(a1p, a1p);
    const ull AP2 = pack2(a2p, a2p), AP3 = pack2(a3p, a3p);
    // ray B
    const ull BF00 = pack2(b0p*b0p, b0p*b0p), BF11 = pack2(b1p*b1p, b1p*b1p);
    const ull BF22 = pack2(b2p*b2p, b2p*b2p), BF33 = pack2(b3p*b3p, b3p*b3p);
    const ull BF01 = pack2(b0p*b1p, b0p*b1p), BF02 = pack2(b0p*b2p, b0p*b2p);
    const ull BF03 = pack2(b0p*b3p, b0p*b3p), BF12 = pack2(b1p*b2p, b1p*b2p);
    const ull BF13 = pack2(b1p*b3p, b1p*b3p), BF23 = pack2(b2p*b3p, b2p*b3p);
    const ull BP0 = pack2(b0p, b0p), BP1 = pack2(b1p, b1p);
    const ull BP2 = pack2(b2p, b2p), BP3 = pack2(b3p, b3p);

    ull accA = pack2(0.0f, 0.0f);
    ull accB = pack2(0.0f, 0.0f);

    const float* tbl = smem_f + spl * ITERS * 32;

    #pragma unroll 1
    for (int q = 0; q < ITERS; q++) {
        const ulonglong2* sp = reinterpret_cast<const ulonglong2*>(tbl + q * 32);

        // stage 1: quad-diagonal coefficients
        ulonglong2 u0 = sp[0];  // C00 | C11
        ulonglong2 u1 = sp[1];  // C22 | C33
        ull x0 = mul2(u0.x, AF00);
        ull x1 = mul2(u0.y, AF11);
        ull y0 = mul2(u0.x, BF00);
        ull y1 = mul2(u0.y, BF11);
        x0 = fma2(u1.x, AF22, x0);
        x1 = fma2(u1.y, AF33, x1);
        y0 = fma2(u1.x, BF22, y0);
        y1 = fma2(u1.y, BF33, y1);

        // stage 2: cross terms 01,02,03,12
        u0 = sp[2];  u1 = sp[3];
        x0 = fma2(u0.x, AF01, x0);
        x1 = fma2(u0.y, AF02, x1);
        y0 = fma2(u0.x, BF01, y0);
        y1 = fma2(u0.y, BF02, y1);
        x0 = fma2(u1.x, AF03, x0);
        x1 = fma2(u1.y, AF12, x1);
        y0 = fma2(u1.x, BF03, y0);
        y1 = fma2(u1.y, BF12, y1);

        // stage 3: cross 13,23 + linear l0,l1
        u0 = sp[4];  u1 = sp[5];
        x0 = fma2(u0.x, AF13, x0);
        x1 = fma2(u0.y, AF23, x1);
        y0 = fma2(u0.x, BF13, y0);
        y1 = fma2(u0.y, BF23, y1);
        x0 = fma2(u1.x, AP0, x0);
        x1 = fma2(u1.y, AP1, x1);
        y0 = fma2(u1.x, BP0, y0);
        y1 = fma2(u1.y, BP1, y1);

        // stage 4: linear l2,l3 + const + label
        u0 = sp[6];  u1 = sp[7];
        x0 = fma2(u0.x, AP2, x0);
        x1 = fma2(u0.y, AP3, x1);
        y0 = fma2(u0.x, BP2, y0);
        y1 = fma2(u0.y, BP3, y1);
        x0 = add2(x0, u1.x);           // + const
        y0 = add2(y0, u1.x);
        const ull tA = add2(x0, x1);
        const ull tB = add2(y0, y1);

        float ta0, ta1, tb0, tb1;
        unpack2(tA, ta0, ta1);
        unpack2(tB, tb0, tb1);
        float ea0, ea1, eb0, eb1;
        asm("ex2.approx.ftz.f32 %0, %1;" : "=f"(ea0) : "f"(ta0));
        asm("ex2.approx.ftz.f32 %0, %1;" : "=f"(ea1) : "f"(ta1));
        asm("ex2.approx.ftz.f32 %0, %1;" : "=f"(eb0) : "f"(tb0));
        asm("ex2.approx.ftz.f32 %0, %1;" : "=f"(eb1) : "f"(tb1));
        accA = fma2(u1.y, pack2(ea0, ea1), accA);
        accB = fma2(u1.y, pack2(eb0, eb1), accB);
    }

    float sa0, sa1, sb0, sb1;
    unpack2(accA, sa0, sa1);
    unpack2(accB, sb0, sb1);
    s_red[spl * RAYS_PER_BLOCK + slot]         = sa0 + sa1;
    s_red[spl * RAYS_PER_BLOCK + SLOTS + slot] = sb0 + sb1;
    __syncthreads();

    if (tid < RAYS_PER_BLOCK) {
        float accT = 0.0f;
        #pragma unroll
        for (int s = 0; s < SPLITS; s++)
            accT += s_red[s * RAYS_PER_BLOCK + tid];
        const float z = -accT * 1.4426950408889634f;
        float em;
        asm("ex2.approx.ftz.f32 %0, %1;" : "=f"(em) : "f"(z));
        float prob;
        asm("rcp.approx.ftz.f32 %0, %1;" : "=f"(prob) : "f"(1.0f + em));
        out[base + tid] = prob;
    }
}

// ---------------------------------------------------------------------------
extern "C" void kernel_launch(void* const* d_in, const int* in_sizes, int n_in,
                              void* d_out, int out_size) {
    const float* origins    = (const float*)d_in[0];
    const float* directions = (const float*)d_in[1];
    const float* means      = (const float*)d_in[2];
    const float* covs       = (const float*)d_in[3];
    const float* labels     = (const float*)d_in[4];
    float* out = (float*)d_out;

    prep_kernel<<<32, 32>>>(means, covs, labels);

    const int smem_bytes = (TBL_FLOATS + 512) * (int)sizeof(float);
    cudaFuncSetAttribute(decoder_kernel,
                         cudaFuncAttributeMaxDynamicSharedMemorySize, smem_bytes);
    decoder_kernel<<<N_RAYS / RAYS_PER_BLOCK, 256, smem_bytes>>>(origins, directions, out);
}

// round 7
// speedup vs baseline: 1.5768x; 1.5768x over previous
#include <cuda_runtime.h>
#include <cuda_bf16.h>
#include <cstdint>

#define N_RAYS 32768
#define M_G    1024
#define NTILES (M_G / 8)       // 128 n-tiles of 8 gaussians
#define KSTEPS 3               // K = 48 = 3 x k16 (bf16 hi/lo split)
#define WARPS  8
#define RAYS_PER_WARP 16
#define RAYS_PER_BLOCK (WARPS * RAYS_PER_WARP)   // 128

typedef unsigned int u32;
typedef unsigned long long ull;

// B fragment table, prebuilt in the exact m16n8k16 lane layout:
//   g_tblB[(t*3 + s)*32 + lane] = { b0, b1 } for warp-lane `lane`, n-tile t,
//   k-step s.  b0 = W2[n][16s+2tig .. +1], b1 = W2[n][16s+2tig+8 .. +9],
//   n = t*8 + (lane>>2), tig = lane&3, packed bf16x2 (low = even k).
//   W2 k-layout: [0..15]=hi, [16..31]=hi, [32..47]=lo.
__device__ __align__(16) ull g_tblB[NTILES * KSTEPS * 32];   // 96 KB

__device__ __forceinline__ u32 pack_bf16x2(float a, float b) {
    __nv_bfloat16 x = __float2bfloat16(a), y = __float2bfloat16(b);
    return (u32)__bfloat16_as_ushort(x) | ((u32)__bfloat16_as_ushort(y) << 16);
}

// ---------------------------------------------------------------------------
// Prep: invert Sigma (fp32 GJ + one Newton step), fold -0.5*log2(e) and mean
// into 16 coefficients, split bf16 hi/lo, emit B-fragment table entries.
// ---------------------------------------------------------------------------
__global__ void prep_kernel(const float* __restrict__ means,
                            const float* __restrict__ covs) {
    int m = blockIdx.x * blockDim.x + threadIdx.x;
    if (m >= M_G) return;

    float S[4][4], a[4][8];
    #pragma unroll
    for (int i = 0; i < 4; i++)
        #pragma unroll
        for (int j = 0; j < 4; j++) {
            S[i][j] = covs[m * 16 + i * 4 + j];
            a[i][j] = S[i][j];
        }
    #pragma unroll
    for (int i = 0; i < 4; i++)
        #pragma unroll
        for (int j = 0; j < 4; j++) a[i][4 + j] = (i == j) ? 1.0f : 0.0f;
    #pragma unroll
    for (int c = 0; c < 4; c++) {
        float inv = __frcp_rn(a[c][c]);
        #pragma unroll
        for (int j = 0; j < 8; j++) a[c][j] *= inv;
        #pragma unroll
        for (int r = 0; r < 4; r++) {
            if (r == c) continue;
            float f = a[r][c];
            #pragma unroll
            for (int j = 0; j < 8; j++) a[r][j] = fmaf(-f, a[c][j], a[r][j]);
        }
    }
    float X[4][4], T[4][4], Xr[4][4];
    #pragma unroll
    for (int i = 0; i < 4; i++)
        #pragma unroll
        for (int j = 0; j < 4; j++) X[i][j] = a[i][4 + j];
    #pragma unroll
    for (int i = 0; i < 4; i++)
        #pragma unroll
        for (int j = 0; j < 4; j++) {
            float s = (i == j) ? 2.0f : 0.0f;
            #pragma unroll
            for (int k = 0; k < 4; k++) s = fmaf(-S[i][k], X[k][j], s);
            T[i][j] = s;
        }
    #pragma unroll
    for (int i = 0; i < 4; i++)
        #pragma unroll
        for (int j = 0; j < 4; j++) {
            float s = 0.0f;
            #pragma unroll
            for (int k = 0; k < 4; k++) s = fmaf(X[i][k], T[k][j], s);
            Xr[i][j] = s;
        }
    const float kk = -0.5f * 1.4426950408889634f;   // -0.5*log2(e)
    float C[4][4];
    #pragma unroll
    for (int i = 0; i < 4; i++)
        #pragma unroll
        for (int j = 0; j < 4; j++) C[i][j] = kk * Xr[i][j];
    float mu[4];
    #pragma unroll
    for (int i = 0; i < 4; i++) mu[i] = means[m * 4 + i];

    float w[16];
    w[0] = C[0][0]; w[1] = C[1][1]; w[2] = C[2][2]; w[3] = C[3][3];
    w[4] = 2.0f * C[0][1]; w[5] = 2.0f * C[0][2]; w[6] = 2.0f * C[0][3];
    w[7] = 2.0f * C[1][2]; w[8] = 2.0f * C[1][3]; w[9] = 2.0f * C[2][3];
    #pragma unroll
    for (int i = 0; i < 4; i++) {
        float s = 0.0f;
        #pragma unroll
        for (int j = 0; j < 4; j++) s = fmaf(C[i][j], mu[j], s);
        w[10 + i] = -2.0f * s;
    }
    float q = 0.0f;
    #pragma unroll
    for (int i = 0; i < 4; i++) {
        float s = 0.0f;
        #pragma unroll
        for (int j = 0; j < 4; j++) s = fmaf(C[i][j], mu[j], s);
        q = fmaf(mu[i], s, q);
    }
    w[14] = q;
    w[15] = 0.0f;

    float hi[16], lo[16];
    #pragma unroll
    for (int k = 0; k < 16; k++) {
        __nv_bfloat16 h = __float2bfloat16(w[k]);
        hi[k] = __bfloat162float(h);
        lo[k] = w[k] - hi[k];
    }

    // B-fragment entries for this gaussian (column j of tile t)
    const int t = m >> 3, j = m & 7;
    #pragma unroll
    for (int tig = 0; tig < 4; tig++) {
        u32 h0 = pack_bf16x2(hi[2 * tig],     hi[2 * tig + 1]);
        u32 h1 = pack_bf16x2(hi[2 * tig + 8], hi[2 * tig + 9]);
        u32 l0 = pack_bf16x2(lo[2 * tig],     lo[2 * tig + 1]);
        u32 l1 = pack_bf16x2(lo[2 * tig + 8], lo[2 * tig + 9]);
        ull hh = (ull)h0 | ((ull)h1 << 32);
        ull ll = (ull)l0 | ((ull)l1 << 32);
        const int lane = 4 * j + tig;
        g_tblB[(t * 3 + 0) * 32 + lane] = hh;   // s=0: B hi
        g_tblB[(t * 3 + 1) * 32 + lane] = hh;   // s=1: B hi (vs A lo)
        g_tblB[(t * 3 + 2) * 32 + lane] = ll;   // s=2: B lo (vs A hi)
    }
}

// ---------------------------------------------------------------------------
// Decoder: 256 threads = 8 warps x 16 rays; per warp 128 n-tiles of
// m16n8k16 bf16 mma.sync (3 k-steps) + ex2/label epilogue in registers.
// SMEM: 96KB B-frag table + 4KB labels + 12.5KB A staging.
// ---------------------------------------------------------------------------
#define SM_TBL   0
#define SM_LAB   (NTILES * KSTEPS * 32 * 8)          // 98304
#define SM_STAGE (SM_LAB + M_G * 4)                  // 102400
#define STAGE_W  25                                  // padded words per ray
#define SM_TOTAL (SM_STAGE + WARPS * RAYS_PER_WARP * STAGE_W * 4)  // 115200

extern __shared__ unsigned char smem_raw[];

__device__ __forceinline__ void mma16816(float& c0, float& c1, float& c2, float& c3,
                                         u32 a0, u32 a1, u32 a2, u32 a3,
                                         u32 b0, u32 b1) {
    asm volatile(
        "mma.sync.aligned.m16n8k16.row.col.f32.bf16.bf16.f32 "
        "{%0,%1,%2,%3}, {%4,%5,%6,%7}, {%8,%9}, {%0,%1,%2,%3};"
        : "+f"(c0), "+f"(c1), "+f"(c2), "+f"(c3)
        : "r"(a0), "r"(a1), "r"(a2), "r"(a3), "r"(b0), "r"(b1));
}

__global__ void __launch_bounds__(256, 2)
decoder_kernel(const float* __restrict__ origins,
               const float* __restrict__ dirs,
               const float* __restrict__ labels,
               float* __restrict__ out) {
    const int tid  = threadIdx.x;
    const int wid  = tid >> 5;
    const int lane = tid & 31;
    const int gid  = lane >> 2;   // row group 0..7
    const int tig  = lane & 3;    // thread-in-group

    // ---- cooperative copies: B table (96KB) + labels (4KB) ----
    {
        const uint4* gt = reinterpret_cast<const uint4*>(g_tblB);
        uint4* st = reinterpret_cast<uint4*>(smem_raw + SM_TBL);
        #pragma unroll
        for (int i = 0; i < (NTILES * KSTEPS * 32 * 8 / 16) / 256; i++)
            st[tid + i * 256] = gt[tid + i * 256];
        const uint4* gl = reinterpret_cast<const uint4*>(labels);
        uint4* sl = reinterpret_cast<uint4*>(smem_raw + SM_LAB);
        sl[tid] = gl[tid];   // 1024 floats = 256 uint4
    }

    // ---- A staging: lanes 0..15 build their ray's 24-word K vector ----
    u32* stage = reinterpret_cast<u32*>(smem_raw + SM_STAGE) +
                 wid * RAYS_PER_WARP * STAGE_W;
    const int ray_base = blockIdx.x * RAYS_PER_BLOCK + wid * RAYS_PER_WARP;
    if (lane < 16) {
        const int n = ray_base + lane;
        const float2 o = reinterpret_cast<const float2*>(origins)[n];
        const float2 d = reinterpret_cast<const float2*>(dirs)[n];
        const float p0 = o.x, p1 = o.y, p2 = d.x, p3 = d.y;
        float phi[16];
        phi[0] = p0 * p0; phi[1] = p1 * p1; phi[2] = p2 * p2; phi[3] = p3 * p3;
        phi[4] = p0 * p1; phi[5] = p0 * p2; phi[6] = p0 * p3;
        phi[7] = p1 * p2; phi[8] = p1 * p3; phi[9] = p2 * p3;
        phi[10] = p0; phi[11] = p1; phi[12] = p2; phi[13] = p3;
        phi[14] = 1.0f; phi[15] = 0.0f;
        float hi[16], lo[16];
        #pragma unroll
        for (int k = 0; k < 16; k++) {
            __nv_bfloat16 h = __float2bfloat16(phi[k]);
            hi[k] = __bfloat162float(h);
            lo[k] = phi[k] - hi[k];
        }
        u32* row = stage + lane * STAGE_W;
        #pragma unroll
        for (int wd = 0; wd < 8; wd++) {
            u32 ph = pack_bf16x2(hi[2 * wd], hi[2 * wd + 1]);
            u32 pl = pack_bf16x2(lo[2 * wd], lo[2 * wd + 1]);
            row[wd]      = ph;   // k[0..15]  = hi
            row[8 + wd]  = pl;   // k[16..31] = lo
            row[16 + wd] = ph;   // k[32..47] = hi
        }
    }
    __syncthreads();   // table + labels + staging all visible

    // ---- load A fragments (12 words, once) ----
    u32 afr[KSTEPS][4];
    #pragma unroll
    for (int s = 0; s < KSTEPS; s++) {
        afr[s][0] = stage[gid * STAGE_W       + 8 * s + tig];
        afr[s][1] = stage[(gid + 8) * STAGE_W + 8 * s + tig];
        afr[s][2] = stage[gid * STAGE_W       + 8 * s + tig + 4];
        afr[s][3] = stage[(gid + 8) * STAGE_W + 8 * s + tig + 4];
    }

    const ull* tbl = reinterpret_cast<const ull*>(smem_raw + SM_TBL);
    const float2* lab2 = reinterpret_cast<const float2*>(smem_raw + SM_LAB);

    float accLo = 0.0f, accHi = 0.0f;

    #pragma unroll 4
    for (int t = 0; t < NTILES; t++) {
        const ull* bt = tbl + t * (KSTEPS * 32) + lane;
        const ull b0v = bt[0];
        const ull b1v = bt[32];
        const ull b2v = bt[64];

        float c0 = 0.0f, c1 = 0.0f, c2 = 0.0f, c3 = 0.0f;
        mma16816(c0, c1, c2, c3, afr[0][0], afr[0][1], afr[0][2], afr[0][3],
                 (u32)b0v, (u32)(b0v >> 32));
        mma16816(c0, c1, c2, c3, afr[1][0], afr[1][1], afr[1][2], afr[1][3],
                 (u32)b1v, (u32)(b1v >> 32));
        mma16816(c0, c1, c2, c3, afr[2][0], afr[2][1], afr[2][2], afr[2][3],
                 (u32)b2v, (u32)(b2v >> 32));

        // epilogue: gaussians g = t*8 + 2*tig, +1 for rays gid / gid+8
        const float2 L = lab2[t * 4 + tig];
        float e0, e1, e2, e3;
        asm("ex2.approx.ftz.f32 %0, %1;" : "=f"(e0) : "f"(c0));
        asm("ex2.approx.ftz.f32 %0, %1;" : "=f"(e1) : "f"(c1));
        asm("ex2.approx.ftz.f32 %0, %1;" : "=f"(e2) : "f"(c2));
        asm("ex2.approx.ftz.f32 %0, %1;" : "=f"(e3) : "f"(c3));
        accLo = fmaf(L.x, e0, accLo);
        accLo = fmaf(L.y, e1, accLo);
        accHi = fmaf(L.x, e2, accHi);
        accHi = fmaf(L.y, e3, accHi);
    }

    // ---- reduce across the 4 lanes of each row group ----
    #pragma unroll
    for (int d = 1; d < 4; d <<= 1) {
        accLo += __shfl_xor_sync(0xffffffffu, accLo, d);
        accHi += __shfl_xor_sync(0xffffffffu, accHi, d);
    }

    if (tig == 0) {
        const float zL = -accLo * 1.4426950408889634f;
        const float zH = -accHi * 1.4426950408889634f;
        float eL, eH, pL, pH;
        asm("ex2.approx.ftz.f32 %0, %1;" : "=f"(eL) : "f"(zL));
        asm("ex2.approx.ftz.f32 %0, %1;" : "=f"(eH) : "f"(zH));
        asm("rcp.approx.ftz.f32 %0, %1;" : "=f"(pL) : "f"(1.0f + eL));
        asm("rcp.approx.ftz.f32 %0, %1;" : "=f"(pH) : "f"(1.0f + eH));
        out[ray_base + gid]     = pL;
        out[ray_base + gid + 8] = pH;
    }
}

// ---------------------------------------------------------------------------
extern "C" void kernel_launch(void* const* d_in, const int* in_sizes, int n_in,
                              void* d_out, int out_size) {
    const float* origins    = (const float*)d_in[0];
    const float* directions = (const float*)d_in[1];
    const float* means      = (const float*)d_in[2];
    const float* covs       = (const float*)d_in[3];
    const float* labels     = (const float*)d_in[4];
    float* out = (float*)d_out;

    prep_kernel<<<8, 128>>>(means, covs);

    cudaFuncSetAttribute(decoder_kernel,
                         cudaFuncAttributeMaxDynamicSharedMemorySize, SM_TOTAL);
    decoder_kernel<<<N_RAYS / RAYS_PER_BLOCK, 256, SM_TOTAL>>>(
        origins, directions, labels, out);
}

// round 8
// speedup vs baseline: 1.5792x; 1.0015x over previous
#include <cuda_runtime.h>
#include <cuda_bf16.h>
#include <cstdint>

#define N_RAYS 32768
#define M_G    1024
#define NTILES (M_G / 8)       // 128 n-tiles of 8 gaussians
#define WARPS  8
#define RAYS_PER_WARP 16
#define RAYS_PER_BLOCK (WARPS * RAYS_PER_WARP)   // 128

typedef unsigned int u32;
typedef unsigned long long ull;

// B fragment table in m16n8k16 lane layout, deduplicated:
//   g_tblB[(t*2 + s)*32 + lane], s=0 -> hi coefficients (used by K-steps 0 and 1),
//   s=1 -> lo coefficients (K-step 2). Each entry: {b0,b1} bf16x2 pair for
//   gaussian n = t*8 + (lane>>2), k-halves 2*(lane&3)(+1) and +8.
__device__ __align__(16) ull g_tblB[NTILES * 2 * 32];   // 64 KB

__device__ __forceinline__ u32 pack_bf16x2(float a, float b) {
    __nv_bfloat16 x = __float2bfloat16(a), y = __float2bfloat16(b);
    return (u32)__bfloat16_as_ushort(x) | ((u32)__bfloat16_as_ushort(y) << 16);
}

// ---------------------------------------------------------------------------
// Prep: invert Sigma (fp32 GJ + one Newton step), fold -0.5*log2(e) and mean
// into 16 coefficients, split bf16 hi/lo, emit deduped B-fragment entries.
// ---------------------------------------------------------------------------
__global__ void prep_kernel(const float* __restrict__ means,
                            const float* __restrict__ covs) {
    int m = blockIdx.x * blockDim.x + threadIdx.x;
    if (m >= M_G) return;

    float S[4][4], a[4][8];
    #pragma unroll
    for (int i = 0; i < 4; i++)
        #pragma unroll
        for (int j = 0; j < 4; j++) {
            S[i][j] = covs[m * 16 + i * 4 + j];
            a[i][j] = S[i][j];
        }
    #pragma unroll
    for (int i = 0; i < 4; i++)
        #pragma unroll
        for (int j = 0; j < 4; j++) a[i][4 + j] = (i == j) ? 1.0f : 0.0f;
    #pragma unroll
    for (int c = 0; c < 4; c++) {
        float inv = __frcp_rn(a[c][c]);
        #pragma unroll
        for (int j = 0; j < 8; j++) a[c][j] *= inv;
        #pragma unroll
        for (int r = 0; r < 4; r++) {
            if (r == c) continue;
            float f = a[r][c];
            #pragma unroll
            for (int j = 0; j < 8; j++) a[r][j] = fmaf(-f, a[c][j], a[r][j]);
        }
    }
    float X[4][4], T[4][4], Xr[4][4];
    #pragma unroll
    for (int i = 0; i < 4; i++)
        #pragma unroll
        for (int j = 0; j < 4; j++) X[i][j] = a[i][4 + j];
    #pragma unroll
    for (int i = 0; i < 4; i++)
        #pragma unroll
        for (int j = 0; j < 4; j++) {
            float s = (i == j) ? 2.0f : 0.0f;
            #pragma unroll
            for (int k = 0; k < 4; k++) s = fmaf(-S[i][k], X[k][j], s);
            T[i][j] = s;
        }
    #pragma unroll
    for (int i = 0; i < 4; i++)
        #pragma unroll
        for (int j = 0; j < 4; j++) {
            float s = 0.0f;
            #pragma unroll
            for (int k = 0; k < 4; k++) s = fmaf(X[i][k], T[k][j], s);
            Xr[i][j] = s;
        }
    const float kk = -0.5f * 1.4426950408889634f;   // -0.5*log2(e)
    float C[4][4];
    #pragma unroll
    for (int i = 0; i < 4; i++)
        #pragma unroll
        for (int j = 0; j < 4; j++) C[i][j] = kk * Xr[i][j];
    float mu[4];
    #pragma unroll
    for (int i = 0; i < 4; i++) mu[i] = means[m * 4 + i];

    float w[16];
    w[0] = C[0][0]; w[1] = C[1][1]; w[2] = C[2][2]; w[3] = C[3][3];
    w[4] = 2.0f * C[0][1]; w[5] = 2.0f * C[0][2]; w[6] = 2.0f * C[0][3];
    w[7] = 2.0f * C[1][2]; w[8] = 2.0f * C[1][3]; w[9] = 2.0f * C[2][3];
    #pragma unroll
    for (int i = 0; i < 4; i++) {
        float s = 0.0f;
        #pragma unroll
        for (int j = 0; j < 4; j++) s = fmaf(C[i][j], mu[j], s);
        w[10 + i] = -2.0f * s;
    }
    float q = 0.0f;
    #pragma unroll
    for (int i = 0; i < 4; i++) {
        float s = 0.0f;
        #pragma unroll
        for (int j = 0; j < 4; j++) s = fmaf(C[i][j], mu[j], s);
        q = fmaf(mu[i], s, q);
    }
    w[14] = q;
    w[15] = 0.0f;

    float hi[16], lo[16];
    #pragma unroll
    for (int k = 0; k < 16; k++) {
        __nv_bfloat16 h = __float2bfloat16(w[k]);
        hi[k] = __bfloat162float(h);
        lo[k] = w[k] - hi[k];
    }

    const int t = m >> 3, j = m & 7;
    #pragma unroll
    for (int tig = 0; tig < 4; tig++) {
        u32 h0 = pack_bf16x2(hi[2 * tig],     hi[2 * tig + 1]);
        u32 h1 = pack_bf16x2(hi[2 * tig + 8], hi[2 * tig + 9]);
        u32 l0 = pack_bf16x2(lo[2 * tig],     lo[2 * tig + 1]);
        u32 l1 = pack_bf16x2(lo[2 * tig + 8], lo[2 * tig + 9]);
        const int lane = 4 * j + tig;
        g_tblB[(t * 2 + 0) * 32 + lane] = (ull)h0 | ((ull)h1 << 32);  // hi
        g_tblB[(t * 2 + 1) * 32 + lane] = (ull)l0 | ((ull)l1 << 32);  // lo
    }
}

// ---------------------------------------------------------------------------
// Decoder: 256 threads = 8 warps x 16 rays; per warp 128 n-tiles of
// m16n8k16 bf16 mma.sync (hi*hi | lo*hi -> hi*lo split chains) + ex2/label
// epilogue. SMEM: 64KB table + 4KB labels + 12.8KB A staging -> 2 CTA/SM.
// ---------------------------------------------------------------------------
#define SM_TBL   0
#define SM_LAB   (NTILES * 2 * 32 * 8)               // 65536
#define SM_STAGE (SM_LAB + M_G * 4)                  // 69632
#define STAGE_W  25                                  // padded words per ray
#define SM_TOTAL (SM_STAGE + RAYS_PER_BLOCK * STAGE_W * 4)  // 82432

extern __shared__ unsigned char smem_raw[];

__device__ __forceinline__ void mma16816(float& c0, float& c1, float& c2, float& c3,
                                         u32 a0, u32 a1, u32 a2, u32 a3,
                                         u32 b0, u32 b1) {
    asm volatile(
        "mma.sync.aligned.m16n8k16.row.col.f32.bf16.bf16.f32 "
        "{%0,%1,%2,%3}, {%4,%5,%6,%7}, {%8,%9}, {%0,%1,%2,%3};"
        : "+f"(c0), "+f"(c1), "+f"(c2), "+f"(c3)
        : "r"(a0), "r"(a1), "r"(a2), "r"(a3), "r"(b0), "r"(b1));
}

__global__ void __launch_bounds__(256, 2)
decoder_kernel(const float* __restrict__ origins,
               const float* __restrict__ dirs,
               const float* __restrict__ labels,
               float* __restrict__ out) {
    const int tid  = threadIdx.x;
    const int wid  = tid >> 5;
    const int lane = tid & 31;
    const int gid  = lane >> 2;   // row group 0..7
    const int tig  = lane & 3;    // thread-in-group

    // ---- cooperative copies: B table (64KB) + labels (4KB) ----
    {
        const uint4* gt = reinterpret_cast<const uint4*>(g_tblB);
        uint4* st = reinterpret_cast<uint4*>(smem_raw + SM_TBL);
        #pragma unroll
        for (int i = 0; i < (NTILES * 2 * 32 * 8 / 16) / 256; i++)
            st[tid + i * 256] = gt[tid + i * 256];
        const uint4* gl = reinterpret_cast<const uint4*>(labels);
        uint4* sl = reinterpret_cast<uint4*>(smem_raw + SM_LAB);
        sl[tid] = gl[tid];   // 1024 floats = 256 uint4
    }

    // ---- A staging: lanes 0..15 build their ray's 24-word K vector ----
    u32* stage = reinterpret_cast<u32*>(smem_raw + SM_STAGE) +
                 wid * RAYS_PER_WARP * STAGE_W;
    const int ray_base = blockIdx.x * RAYS_PER_BLOCK + wid * RAYS_PER_WARP;
    if (lane < 16) {
        const int n = ray_base + lane;
        const float2 o = reinterpret_cast<const float2*>(origins)[n];
        const float2 d = reinterpret_cast<const float2*>(dirs)[n];
        const float p0 = o.x, p1 = o.y, p2 = d.x, p3 = d.y;
        float phi[16];
        phi[0] = p0 * p0; phi[1] = p1 * p1; phi[2] = p2 * p2; phi[3] = p3 * p3;
        phi[4] = p0 * p1; phi[5] = p0 * p2; phi[6] = p0 * p3;
        phi[7] = p1 * p2; phi[8] = p1 * p3; phi[9] = p2 * p3;
        phi[10] = p0; phi[11] = p1; phi[12] = p2; phi[13] = p3;
        phi[14] = 1.0f; phi[15] = 0.0f;
        float hi[16], lo[16];
        #pragma unroll
        for (int k = 0; k < 16; k++) {
            __nv_bfloat16 h = __float2bfloat16(phi[k]);
            hi[k] = __bfloat162float(h);
            lo[k] = phi[k] - hi[k];
        }
        u32* row = stage + lane * STAGE_W;
        #pragma unroll
        for (int wd = 0; wd < 8; wd++) {
            row[wd]      = pack_bf16x2(hi[2 * wd], hi[2 * wd + 1]);  // k[0..15]
            row[8 + wd]  = pack_bf16x2(lo[2 * wd], lo[2 * wd + 1]);  // k[16..31]
            row[16 + wd] = row[wd];                                   // k[32..47]
        }
    }
    __syncthreads();

    // ---- load A fragments (12 words, once) ----
    u32 afr[3][4];
    #pragma unroll
    for (int s = 0; s < 3; s++) {
        afr[s][0] = stage[gid * STAGE_W       + 8 * s + tig];
        afr[s][1] = stage[(gid + 8) * STAGE_W + 8 * s + tig];
        afr[s][2] = stage[gid * STAGE_W       + 8 * s + tig + 4];
        afr[s][3] = stage[(gid + 8) * STAGE_W + 8 * s + tig + 4];
    }

    const ull* tbl = reinterpret_cast<const ull*>(smem_raw + SM_TBL);
    const float2* lab2 = reinterpret_cast<const float2*>(smem_raw + SM_LAB);

    float accLo0 = 0.0f, accLo1 = 0.0f, accHi0 = 0.0f, accHi1 = 0.0f;

    #pragma unroll 4
    for (int t = 0; t < NTILES; t++) {
        const ull* bt = tbl + t * 64 + lane;
        const ull hhv = bt[0];
        const ull llv = bt[32];
        const u32 hh0 = (u32)hhv, hh1 = (u32)(hhv >> 32);
        const u32 ll0 = (u32)llv, ll1 = (u32)(llv >> 32);

        // chain A: hi*hi (1 MMA); chain B: lo*hi -> hi*lo (2 MMAs)
        float cA0 = 0.0f, cA1 = 0.0f, cA2 = 0.0f, cA3 = 0.0f;
        float cB0 = 0.0f, cB1 = 0.0f, cB2 = 0.0f, cB3 = 0.0f;
        mma16816(cA0, cA1, cA2, cA3, afr[0][0], afr[0][1], afr[0][2], afr[0][3],
                 hh0, hh1);
        mma16816(cB0, cB1, cB2, cB3, afr[1][0], afr[1][1], afr[1][2], afr[1][3],
                 hh0, hh1);
        mma16816(cB0, cB1, cB2, cB3, afr[2][0], afr[2][1], afr[2][2], afr[2][3],
                 ll0, ll1);

        const float2 L = lab2[t * 4 + tig];
        float e0, e1, e2, e3;
        asm("ex2.approx.ftz.f32 %0, %1;" : "=f"(e0) : "f"(cA0 + cB0));
        asm("ex2.approx.ftz.f32 %0, %1;" : "=f"(e1) : "f"(cA1 + cB1));
        asm("ex2.approx.ftz.f32 %0, %1;" : "=f"(e2) : "f"(cA2 + cB2));
        asm("ex2.approx.ftz.f32 %0, %1;" : "=f"(e3) : "f"(cA3 + cB3));
        accLo0 = fmaf(L.x, e0, accLo0);
        accLo1 = fmaf(L.y, e1, accLo1);
        accHi0 = fmaf(L.x, e2, accHi0);
        accHi1 = fmaf(L.y, e3, accHi1);
    }

    float accLo = accLo0 + accLo1;
    float accHi = accHi0 + accHi1;

    // ---- reduce across the 4 lanes of each row group ----
    #pragma unroll
    for (int d = 1; d < 4; d <<= 1) {
        accLo += __shfl_xor_sync(0xffffffffu, accLo, d);
        accHi += __shfl_xor_sync(0xffffffffu, accHi, d);
    }

    if (tig == 0) {
        const float zL = -accLo * 1.4426950408889634f;
        const float zH = -accHi * 1.4426950408889634f;
        float eL, eH, pL, pH;
        asm("ex2.approx.ftz.f32 %0, %1;" : "=f"(eL) : "f"(zL));
        asm("ex2.approx.ftz.f32 %0, %1;" : "=f"(eH) : "f"(zH));
        asm("rcp.approx.ftz.f32 %0, %1;" : "=f"(pL) : "f"(1.0f + eL));
        asm("rcp.approx.ftz.f32 %0, %1;" : "=f"(pH) : "f"(1.0f + eH));
        out[ray_base + gid]     = pL;
        out[ray_base + gid + 8] = pH;
    }
}

// ---------------------------------------------------------------------------
extern "C" void kernel_launch(void* const* d_in, const int* in_sizes, int n_in,
                              void* d_out, int out_size) {
    const float* origins    = (const float*)d_in[0];
    const float* directions = (const float*)d_in[1];
    const float* means      = (const float*)d_in[2];
    const float* covs       = (const float*)d_in[3];
    const float* labels     = (const float*)d_in[4];
    float* out = (float*)d_out;

    prep_kernel<<<8, 128>>>(means, covs);

    cudaFuncSetAttribute(decoder_kernel,
                         cudaFuncAttributeMaxDynamicSharedMemorySize, SM_TOTAL);
    decoder_kernel<<<N_RAYS / RAYS_PER_BLOCK, 256, SM_TOTAL>>>(
        origins, directions, labels, out);
}